// round 1
// baseline (speedup 1.0000x reference)
#include <cuda_runtime.h>
#include <cstdint>

#define B_  32
#define L_  1024
#define D_  1024
#define T_  10
#define M_  (B_*L_)        // 32768 rows
#define NC  32             // padded GEMM cols (30 used: c = t*3+k)
#define CHUNK 64
#define S_  16
#define RPB 151            // recursions per batch: 1 (chunk0) + 15*10 (matrix rows)
#define NREC (B_*RPB)      // 4832

#define LOG2E 1.4426950408889634f
#define LN2   0.6931471805599453f

// ------------------------- device scratch (no allocs allowed) ---------------
__device__ float g_W2[NC*D_];        // repacked weights [c][d]
__device__ float g_Z[(size_t)M_*NC]; // GEMM output
__device__ float g_em2[(size_t)M_*T_]; // emissions * log2e
__device__ float g_T2[T_*T_];        // trans * log2e
__device__ float g_P [T_*T_];        // 2^(trans*log2e) = exp(trans)
__device__ float g_s2[T_];
__device__ float g_e2[T_];
__device__ float g_Mbuf[NREC*T_];    // per-recursion output vectors
__device__ float g_part[B_];

__device__ __forceinline__ float ex2f_(float x){ float r; asm("ex2.approx.f32 %0, %1;" : "=f"(r) : "f"(x)); return r; }
__device__ __forceinline__ float lg2f_(float x){ float r; asm("lg2.approx.f32 %0, %1;" : "=f"(r) : "f"(x)); return r; }

// ------------------------- K1: setup / repack --------------------------------
__global__ void k1_setup(const float* __restrict__ conv_w,
                         const float* __restrict__ start_t,
                         const float* __restrict__ end_t,
                         const float* __restrict__ trans)
{
    int tid = blockIdx.x*blockDim.x + threadIdx.x;
    for (int idx = tid; idx < NC*D_; idx += gridDim.x*blockDim.x){
        int c = idx / D_, d = idx - c*D_;
        float v = 0.f;
        if (c < 30){ int t = c/3, k = c - 3*t; v = conv_w[(t*D_ + d)*3 + k]; }
        g_W2[idx] = v;
    }
    if (tid < T_*T_){ float tv = trans[tid]*LOG2E; g_T2[tid] = tv; g_P[tid] = ex2f_(tv); }
    if (tid < T_){ g_s2[tid] = start_t[tid]*LOG2E; g_e2[tid] = end_t[tid]*LOG2E; }
}

// ------------------------- K2: GEMM  Z[m][c] = X[m,:] . W2[c,:] --------------
// block: 128 threads, tile 64 rows x 32 cols. thread-tile 4x4.
// rows of a thread: rowg + 16*r (interleaved).  A from global via L1, B staged.
__global__ void __launch_bounds__(128) k2_gemm(const float* __restrict__ X)
{
    __shared__ float bs[32][36];   // [kk][c], padded
    const int tid  = threadIdx.x;
    const int rowg = tid & 15;
    const int colg = tid >> 4;     // 0..7  -> cols colg*4..+3
    const int rowBase = blockIdx.x * 64;

    float acc[4][4];
#pragma unroll
    for (int r=0;r<4;r++)
#pragma unroll
        for (int c=0;c<4;c++) acc[r][c] = 0.f;

    const float* x0 = X + (size_t)(rowBase + rowg) * D_;

    for (int k0 = 0; k0 < D_; k0 += 32){
        __syncthreads();
#pragma unroll
        for (int e=0;e<8;e++){
            int lin = tid*8 + e;
            int c  = lin >> 5;
            int kk = lin & 31;
            bs[kk][c] = g_W2[c*D_ + k0 + kk];
        }
        __syncthreads();
#pragma unroll
        for (int kk4=0; kk4<8; kk4++){
            float a[4][4];
#pragma unroll
            for (int r=0;r<4;r++){
                float4 v = *reinterpret_cast<const float4*>(x0 + (size_t)r*16*D_ + k0 + kk4*4);
                a[r][0]=v.x; a[r][1]=v.y; a[r][2]=v.z; a[r][3]=v.w;
            }
#pragma unroll
            for (int q=0;q<4;q++){
                int kk = kk4*4+q;
                float b0 = bs[kk][colg*4+0];
                float b1 = bs[kk][colg*4+1];
                float b2 = bs[kk][colg*4+2];
                float b3 = bs[kk][colg*4+3];
#pragma unroll
                for (int r=0;r<4;r++){
                    float av = a[r][q];
                    acc[r][0] += av*b0;
                    acc[r][1] += av*b1;
                    acc[r][2] += av*b2;
                    acc[r][3] += av*b3;
                }
            }
        }
    }
#pragma unroll
    for (int r=0;r<4;r++){
        float4 v; v.x=acc[r][0]; v.y=acc[r][1]; v.z=acc[r][2]; v.w=acc[r][3];
        *reinterpret_cast<float4*>(&g_Z[(size_t)(rowBase+rowg+16*r)*NC + colg*4]) = v;
    }
}

// ------------------------- K3: shifted gather -> em2 = em * log2e ------------
__global__ void k3_gather(const float* __restrict__ conv_b)
{
    int idx = blockIdx.x*blockDim.x + threadIdx.x;
    if (idx >= M_*T_) return;
    int m = idx / T_, t = idx - m*T_;
    int l = m & (L_-1);
    float v = g_Z[(size_t)m*NC + t*3 + 1] + conv_b[t];
    if (l > 0)     v += g_Z[(size_t)(m-1)*NC + t*3 + 0];
    if (l < L_-1)  v += g_Z[(size_t)(m+1)*NC + t*3 + 2];
    g_em2[idx] = v * LOG2E;
}

// ------------------------- K4: chunked CRF recursions ------------------------
// recursion rid -> (b, s, i): rem==0: chunk0 (real alpha), else matrix row i of
// chunk s (1..15). 3 recursions per warp, 10 lanes each; lanes 30/31 idle-run.
__global__ void __launch_bounds__(128) k4_chunks(const int* __restrict__ mask)
{
    int gtid = blockIdx.x*blockDim.x + threadIdx.x;
    int w   = gtid >> 5;
    int lid = gtid & 31;
    int g = lid/10; if (g > 2) g = 2;
    int j = lid - g*10;
    int jc = (j < 10) ? j : 9;
    int rid = w*3 + g;
    bool valid = (rid < NREC) && (j < 10);
    if (rid >= NREC) rid = NREC-1;

    int b   = rid / RPB;
    int rem = rid - b*RPB;
    int s, irow;
    if (rem == 0){ s = 0; irow = 0; }
    else { s = 1 + (rem-1)/10; irow = (rem-1) - ((rem-1)/10)*10; }

    float Pv[10];
#pragma unroll
    for (int k=0;k<10;k++) Pv[k] = g_P[k*10 + jc];

    const float* emB = &g_em2[(size_t)b*L_*T_];
    const int*   mrow = mask + b*L_;

    float a[10], aj;
    if (s == 0){
#pragma unroll
        for (int k=0;k<10;k++) a[k] = g_s2[k] + emB[k];
        aj = g_s2[jc] + emB[jc];
    } else {
#pragma unroll
        for (int k=0;k<10;k++) a[k] = (k==irow) ? 0.f : -1e30f;
        aj = (jc==irow) ? 0.f : -1e30f;
    }

    int lbase = s*CHUNK;
#pragma unroll 1
    for (int it=0; it<CHUNK; it++){
        int l = lbase + it;
        float e  = emB[l*T_ + jc];
        int   mk = mrow[l];

        float mx = a[0];
#pragma unroll
        for (int k=1;k<10;k++) mx = fmaxf(mx, a[k]);

        float sum = 0.f;
#pragma unroll
        for (int k=0;k<10;k++) sum += ex2f_(a[k]-mx) * Pv[k];

        float anew = lg2f_(sum) + mx + e;
        bool skip = (s==0) && (it==0);   // chunk0's step l=0 already in init
        if (mk && !skip) aj = anew;
#pragma unroll
        for (int k=0;k<10;k++) a[k] = __shfl_sync(0xffffffffu, aj, g*10+k);
    }
    if (valid) g_Mbuf[rid*T_ + j] = aj;
}

// ------------------------- K5: sequential combine + numerator ----------------
__global__ void k5_combine(const int* __restrict__ mask, const int* __restrict__ labels)
{
    int b   = blockIdx.x;
    int lid = threadIdx.x;
    bool act = lid < 10;
    int jc = act ? lid : 9;

    float a[10];
    {
        const float* m0 = &g_Mbuf[(size_t)b*RPB*T_];
#pragma unroll
        for (int k=0;k<10;k++) a[k] = m0[k];
    }
    float vj = a[0];
    // own element for lanes<10 (a[] is replicated; grab via shuffle of lane k from a staged broadcast)
    // vj is (re)established inside the combine loop; S_>=2 guarantees it runs.
    for (int s=1; s<S_; s++){
        float t[10];
        float mx = -1e30f;
#pragma unroll
        for (int i=0;i<10;i++){
            t[i] = a[i] + g_Mbuf[((size_t)b*RPB + 1 + (s-1)*10 + i)*T_ + jc];
            mx = fmaxf(mx, t[i]);
        }
        float sum = 0.f;
#pragma unroll
        for (int i=0;i<10;i++) sum += ex2f_(t[i]-mx);
        vj = lg2f_(sum) + mx;
#pragma unroll
        for (int k=0;k<10;k++) a[k] = __shfl_sync(0xffffffffu, vj, k);
    }
    // denom2 = lse2_j(alpha_j + end2_j)
    float v = act ? (vj + g_e2[jc]) : -1e30f;
    float mx = v;
    for (int off=16; off>0; off>>=1) mx = fmaxf(mx, __shfl_xor_sync(0xffffffffu, mx, off));
    float p = act ? ex2f_(v - mx) : 0.f;
    for (int off=16; off>0; off>>=1) p += __shfl_xor_sync(0xffffffffu, p, off);
    float denom2 = lg2f_(p) + mx;

    // numerator (log2 units)
    const int* lb = labels + b*L_;
    const int* mb = mask   + b*L_;
    const float* emB = &g_em2[(size_t)b*L_*T_];
    float nacc = 0.f; int slen = 0;
    for (int l=lid; l<L_; l+=32){
        int ml = mb[l]; slen += ml;
        if (l == 0) nacc += g_s2[lb[0]] + emB[lb[0]];
        else if (ml) nacc += g_T2[lb[l-1]*10 + lb[l]] + emB[l*T_ + lb[l]];
    }
    for (int off=16; off>0; off>>=1){
        nacc += __shfl_xor_sync(0xffffffffu, nacc, off);
        slen += __shfl_xor_sync(0xffffffffu, slen, off);
    }
    float num2 = nacc + g_e2[lb[slen-1]];
    if (lid == 0) g_part[b] = (denom2 - num2) * LN2;
}

// ------------------------- K6: deterministic final reduce --------------------
__global__ void k6_final(float* __restrict__ out)
{
    int lid = threadIdx.x;
    float v = g_part[lid];
    for (int off=16; off>0; off>>=1) v += __shfl_xor_sync(0xffffffffu, v, off);
    if (lid == 0) out[0] = v;
}

// ------------------------- launch --------------------------------------------
extern "C" void kernel_launch(void* const* d_in, const int* in_sizes, int n_in,
                              void* d_out, int out_size)
{
    const float* emb     = (const float*)d_in[0];
    const int*   mask    = (const int*)  d_in[1];
    const int*   labels  = (const int*)  d_in[2];
    const float* conv_w  = (const float*)d_in[3];
    const float* conv_b  = (const float*)d_in[4];
    const float* start_t = (const float*)d_in[5];
    const float* end_t   = (const float*)d_in[6];
    const float* trans   = (const float*)d_in[7];

    k1_setup<<<64, 256>>>(conv_w, start_t, end_t, trans);
    k2_gemm <<<M_/64, 128>>>(emb);
    k3_gather<<<(M_*T_ + 255)/256, 256>>>(conv_b);
    int nwarp = (NREC + 2)/3;
    int nthr  = nwarp*32;
    k4_chunks<<<(nthr + 127)/128, 128>>>(mask);
    k5_combine<<<B_, 32>>>(mask, labels);
    k6_final<<<1, 32>>>((float*)d_out);
}

// round 4
// speedup vs baseline: 3.4060x; 3.4060x over previous
#include <cuda_runtime.h>
#include <cstdint>

#define B_  32
#define L_  1024
#define D_  1024
#define T_  10
#define M_  (B_*L_)
#define NC  32
#define CHUNK 32
#define S_  32
#define RPB 311            // 1 + 31*10
#define NREC (B_*RPB)      // 9952

#define LOG2E 1.4426950408889634f
#define LN2   0.6931471805599453f

// ---------------- device scratch ----------------
__device__ uint32_t g_Wb[32*512];      // weights bf16x2 packed [c][d/2]
__device__ float g_Z[(size_t)M_*NC];
__device__ float g_em2[(size_t)M_*T_];
__device__ float g_T2[T_*T_];
__device__ float g_P [T_*T_];
__device__ float g_s2[T_];
__device__ float g_e2[T_];
__device__ float g_Mbuf[NREC*T_];
__device__ float g_part[B_];

__device__ __forceinline__ float ex2f_(float x){ float r; asm("ex2.approx.f32 %0, %1;" : "=f"(r) : "f"(x)); return r; }
__device__ __forceinline__ float lg2f_(float x){ float r; asm("lg2.approx.f32 %0, %1;" : "=f"(r) : "f"(x)); return r; }

// pack two f32 -> bf16x2, 'lo' in low 16 bits
#define CVT2BF(res, lo, hi) asm("cvt.rn.bf16x2.f32 %0, %1, %2;" : "=r"(res) : "f"(hi), "f"(lo))

__device__ __forceinline__ void mma16816(float c[4], uint32_t a0, uint32_t a1, uint32_t a2, uint32_t a3,
                                         uint32_t b0, uint32_t b1){
    asm volatile("mma.sync.aligned.m16n8k16.row.col.f32.bf16.bf16.f32 "
                 "{%0,%1,%2,%3}, {%4,%5,%6,%7}, {%8,%9}, {%0,%1,%2,%3};"
                 : "+f"(c[0]), "+f"(c[1]), "+f"(c[2]), "+f"(c[3])
                 : "r"(a0), "r"(a1), "r"(a2), "r"(a3), "r"(b0), "r"(b1));
}

// ---------------- K1: setup ----------------
__global__ void k1_setup(const float* __restrict__ conv_w,
                         const float* __restrict__ start_t,
                         const float* __restrict__ end_t,
                         const float* __restrict__ trans)
{
    int tid = blockIdx.x*blockDim.x + threadIdx.x;
    for (int u = tid; u < 32*512; u += gridDim.x*blockDim.x){
        int c = u >> 9, j = u & 511;
        float lo = 0.f, hi = 0.f;
        if (c < 30){
            int t = c/3, kk = c - 3*t;
            lo = conv_w[(t*D_ + 2*j  )*3 + kk];
            hi = conv_w[(t*D_ + 2*j+1)*3 + kk];
        }
        uint32_t p; CVT2BF(p, lo, hi);
        g_Wb[u] = p;
    }
    if (tid < T_*T_){ float tv = trans[tid]*LOG2E; g_T2[tid] = tv; g_P[tid] = ex2f_(tv); }
    if (tid < T_){ g_s2[tid] = start_t[tid]*LOG2E; g_e2[tid] = end_t[tid]*LOG2E; }
}

// ---------------- K2: bf16 HMMA GEMM via mma.sync ----------------
// Z[m][c] = X[m,:].W[c,:]. M=32768, N=32, K=1024.
// CTA: 256 thr / 8 warps, 128-row tile; warp = 16 rows x 32 cols (4 n-tiles).
#define SWS 516   // smem row stride in words (conflict-free: bank = 4g+tg)

__global__ void __launch_bounds__(256) k2_mma(const float* __restrict__ X)
{
    extern __shared__ uint32_t sW[];   // [32][SWS] words
    const int tid = threadIdx.x, wid = tid >> 5, lane = tid & 31;

    for (int idx = tid; idx < 32*512; idx += 256){
        int c = idx >> 9, j = idx & 511;
        sW[c*SWS + j] = g_Wb[idx];
    }
    __syncthreads();

    const int g  = lane >> 2;
    const int tg = lane & 3;
    const int row0 = blockIdx.x*128 + wid*16 + g;
    const float* xr0 = X + (size_t)row0 * D_ + 2*tg;
    const float* xr8 = xr0 + 8*D_;

    float acc[4][4];
#pragma unroll
    for (int n = 0; n < 4; n++)
#pragma unroll
        for (int q = 0; q < 4; q++) acc[n][q] = 0.f;

    const uint32_t* wb0 = &sW[(0*8 + g)*SWS + tg];
    const uint32_t* wb1 = &sW[(1*8 + g)*SWS + tg];
    const uint32_t* wb2 = &sW[(2*8 + g)*SWS + tg];
    const uint32_t* wb3 = &sW[(3*8 + g)*SWS + tg];

#pragma unroll 4
    for (int i = 0; i < 64; i++){
        const int k0 = i*16;
        float2 x0 = *reinterpret_cast<const float2*>(xr0 + k0);
        float2 x1 = *reinterpret_cast<const float2*>(xr8 + k0);
        float2 x2 = *reinterpret_cast<const float2*>(xr0 + k0 + 8);
        float2 x3 = *reinterpret_cast<const float2*>(xr8 + k0 + 8);
        uint32_t a0,a1,a2,a3;
        CVT2BF(a0, x0.x, x0.y);
        CVT2BF(a1, x1.x, x1.y);
        CVT2BF(a2, x2.x, x2.y);
        CVT2BF(a3, x3.x, x3.y);
        const int kh = i*8;
        mma16816(acc[0], a0,a1,a2,a3, wb0[kh], wb0[kh+4]);
        mma16816(acc[1], a0,a1,a2,a3, wb1[kh], wb1[kh+4]);
        mma16816(acc[2], a0,a1,a2,a3, wb2[kh], wb2[kh+4]);
        mma16816(acc[3], a0,a1,a2,a3, wb3[kh], wb3[kh+4]);
    }

    float* z0 = &g_Z[(size_t)row0*NC + 2*tg];
    float* z8 = z0 + 8*NC;
#pragma unroll
    for (int n = 0; n < 4; n++){
        *reinterpret_cast<float2*>(z0 + n*8) = make_float2(acc[n][0], acc[n][1]);
        *reinterpret_cast<float2*>(z8 + n*8) = make_float2(acc[n][2], acc[n][3]);
    }
}

// ---------------- K3: shifted gather -> em2 ----------------
__global__ void k3_gather(const float* __restrict__ conv_b)
{
    int idx = blockIdx.x*blockDim.x + threadIdx.x;
    if (idx >= M_*T_) return;
    int m = idx / T_, t = idx - m*T_;
    int l = m & (L_-1);
    float v = g_Z[(size_t)m*NC + t*3 + 1] + conv_b[t];
    if (l > 0)     v += g_Z[(size_t)(m-1)*NC + t*3 + 0];
    if (l < L_-1)  v += g_Z[(size_t)(m+1)*NC + t*3 + 2];
    g_em2[idx] = v * LOG2E;
}

// ---------------- K4: chunked CRF recursions ----------------
__global__ void __launch_bounds__(128) k4_chunks(const int* __restrict__ mask)
{
    int gtid = blockIdx.x*blockDim.x + threadIdx.x;
    int w   = gtid >> 5;
    int lid = gtid & 31;
    int g = lid/10; if (g > 2) g = 2;
    int j = lid - g*10;
    int jc = (j < 10) ? j : 9;
    int rid = w*3 + g;
    bool valid = (rid < NREC) && (j < 10);
    if (rid >= NREC) rid = NREC-1;

    int b   = rid / RPB;
    int rem = rid - b*RPB;
    int s, irow;
    if (rem == 0){ s = 0; irow = 0; }
    else { s = 1 + (rem-1)/10; irow = (rem-1) - ((rem-1)/10)*10; }

    float Pv[10];
#pragma unroll
    for (int k=0;k<10;k++) Pv[k] = g_P[k*10 + jc];

    const float* emB = &g_em2[(size_t)b*L_*T_];
    const int*   mrow = mask + b*L_;

    float a[10], aj;
    if (s == 0){
#pragma unroll
        for (int k=0;k<10;k++) a[k] = g_s2[k] + emB[k];
        aj = g_s2[jc] + emB[jc];
    } else {
#pragma unroll
        for (int k=0;k<10;k++) a[k] = (k==irow) ? 0.f : -1e30f;
        aj = (jc==irow) ? 0.f : -1e30f;
    }

    int lbase = s*CHUNK;
#pragma unroll 1
    for (int it=0; it<CHUNK; it++){
        int l = lbase + it;
        float e  = emB[l*T_ + jc];
        int   mk = mrow[l];

        float mx = a[0];
#pragma unroll
        for (int k=1;k<10;k++) mx = fmaxf(mx, a[k]);

        float sum = 0.f;
#pragma unroll
        for (int k=0;k<10;k++) sum += ex2f_(a[k]-mx) * Pv[k];

        float anew = lg2f_(sum) + mx + e;
        bool skip = (s==0) && (it==0);
        if (mk && !skip) aj = anew;
#pragma unroll
        for (int k=0;k<10;k++) a[k] = __shfl_sync(0xffffffffu, aj, g*10+k);
    }
    if (valid) g_Mbuf[rid*T_ + j] = aj;
}

// ---------------- K5: combine + numerator ----------------
__global__ void k5_combine(const int* __restrict__ mask, const int* __restrict__ labels)
{
    int b   = blockIdx.x;
    int lid = threadIdx.x;
    bool act = lid < 10;
    int jc = act ? lid : 9;

    float a[10];
    {
        const float* m0 = &g_Mbuf[(size_t)b*RPB*T_];
#pragma unroll
        for (int k=0;k<10;k++) a[k] = m0[k];
    }
    float vj = a[0];
    for (int s=1; s<S_; s++){
        float t[10];
        float mx = -1e30f;
#pragma unroll
        for (int i=0;i<10;i++){
            t[i] = a[i] + g_Mbuf[((size_t)b*RPB + 1 + (s-1)*10 + i)*T_ + jc];
            mx = fmaxf(mx, t[i]);
        }
        float sum = 0.f;
#pragma unroll
        for (int i=0;i<10;i++) sum += ex2f_(t[i]-mx);
        vj = lg2f_(sum) + mx;
#pragma unroll
        for (int k=0;k<10;k++) a[k] = __shfl_sync(0xffffffffu, vj, k);
    }
    float v = act ? (vj + g_e2[jc]) : -1e30f;
    float mx = v;
    for (int off=16; off>0; off>>=1) mx = fmaxf(mx, __shfl_xor_sync(0xffffffffu, mx, off));
    float p = act ? ex2f_(v - mx) : 0.f;
    for (int off=16; off>0; off>>=1) p += __shfl_xor_sync(0xffffffffu, p, off);
    float denom2 = lg2f_(p) + mx;

    const int* lb = labels + b*L_;
    const int* mb = mask   + b*L_;
    const float* emB = &g_em2[(size_t)b*L_*T_];
    float nacc = 0.f; int slen = 0;
    for (int l=lid; l<L_; l+=32){
        int ml = mb[l]; slen += ml;
        if (l == 0) nacc += g_s2[lb[0]] + emB[lb[0]];
        else if (ml) nacc += g_T2[lb[l-1]*10 + lb[l]] + emB[l*T_ + lb[l]];
    }
    for (int off=16; off>0; off>>=1){
        nacc += __shfl_xor_sync(0xffffffffu, nacc, off);
        slen += __shfl_xor_sync(0xffffffffu, slen, off);
    }
    float num2 = nacc + g_e2[lb[slen-1]];
    if (lid == 0) g_part[b] = (denom2 - num2) * LN2;
}

// ---------------- K6: final reduce ----------------
__global__ void k6_final(float* __restrict__ out)
{
    int lid = threadIdx.x;
    float v = g_part[lid];
    for (int off=16; off>0; off>>=1) v += __shfl_xor_sync(0xffffffffu, v, off);
    if (lid == 0) out[0] = v;
}

// ---------------- launch ----------------
extern "C" void kernel_launch(void* const* d_in, const int* in_sizes, int n_in,
                              void* d_out, int out_size)
{
    const float* emb     = (const float*)d_in[0];
    const int*   mask    = (const int*)  d_in[1];
    const int*   labels  = (const int*)  d_in[2];
    const float* conv_w  = (const float*)d_in[3];
    const float* conv_b  = (const float*)d_in[4];
    const float* start_t = (const float*)d_in[5];
    const float* end_t   = (const float*)d_in[6];
    const float* trans   = (const float*)d_in[7];

    const int smem_k2 = 32*SWS*4;
    cudaFuncSetAttribute(k2_mma, cudaFuncAttributeMaxDynamicSharedMemorySize, smem_k2);

    k1_setup<<<64, 256>>>(conv_w, start_t, end_t, trans);
    k2_mma <<<M_/128, 256, smem_k2>>>(emb);
    k3_gather<<<(M_*T_ + 255)/256, 256>>>(conv_b);
    int nwarp = (NREC + 2)/3;
    int nthr  = nwarp*32;
    k4_chunks<<<(nthr + 127)/128, 128>>>(mask);
    k5_combine<<<B_, 32>>>(mask, labels);
    k6_final<<<1, 32>>>((float*)d_out);
}